// round 2
// baseline (speedup 1.0000x reference)
#include <cuda_runtime.h>
#include <math.h>

#define NNODES  1000000
#define HID     256
#define HHALF   128
#define NGRAPH  1024

// ---- scratch (no allocations allowed) ----
__device__ float g_scores[NNODES];   // scores, then exp(score - max)
__device__ float g_segmax[NGRAPH];
__device__ float g_segsum[NGRAPH];

// float atomic max via int/uint monotonic trick
__device__ __forceinline__ void atomicMaxF(float* addr, float v) {
    if (v >= 0.0f) {
        atomicMax((int*)addr, __float_as_int(v));
    } else {
        atomicMin((unsigned int*)addr, __float_as_uint(v));
    }
}

// ---------------------------------------------------------------------------
// K0: init per-graph reductions
// ---------------------------------------------------------------------------
__global__ void k_init() {
    int i = blockIdx.x * blockDim.x + threadIdx.x;
    if (i < NGRAPH) {
        g_segmax[i] = -INFINITY;
        g_segsum[i] = 0.0f;
    }
}

// ---------------------------------------------------------------------------
// K1: fused scores = tanh(x @ w1 + b1) @ w2 + b2, plus per-graph atomicMax.
// Tile: 128 nodes x 128 cols, K=256 in chunks of 32. 256 threads, 8x8 regs.
// ---------------------------------------------------------------------------
#define TM 128
#define KC 32

__global__ __launch_bounds__(256) void k_scores(
    const float* __restrict__ x,
    const int* __restrict__ batch,
    const float* __restrict__ w1,
    const float* __restrict__ b1,
    const float* __restrict__ w2,
    const float* __restrict__ b2,
    int n)
{
    __shared__ float xs[TM][KC + 1];        // 128 x 33
    __shared__ float ws[KC][HHALF + 1];     // 32 x 129
    __shared__ float sred[16][TM + 1];      // 16 x 129 partial row-sums

    const int tid = threadIdx.x;
    const int tx  = tid & 15;   // column group: cols tx*8 .. tx*8+7
    const int ty  = tid >> 4;   // row group:    rows ty*8 .. ty*8+7
    const int row0 = blockIdx.x * TM;

    float acc[8][8];
#pragma unroll
    for (int i = 0; i < 8; i++)
#pragma unroll
        for (int j = 0; j < 8; j++)
            acc[i][j] = 0.0f;

    for (int kk = 0; kk < HID; kk += KC) {
        // load x tile (128 rows x 32 k), zero-padded past n
#pragma unroll
        for (int l = 0; l < 4; l++) {
            int idx = tid + l * 256;          // 0..1023
            int m   = idx >> 3;               // 8 float4 per row
            int c4  = idx & 7;
            int node = row0 + m;
            float4 v = make_float4(0.f, 0.f, 0.f, 0.f);
            if (node < n)
                v = *reinterpret_cast<const float4*>(
                        &x[(size_t)node * HID + kk + c4 * 4]);
            xs[m][c4 * 4 + 0] = v.x;
            xs[m][c4 * 4 + 1] = v.y;
            xs[m][c4 * 4 + 2] = v.z;
            xs[m][c4 * 4 + 3] = v.w;
        }
        // load w1 tile (32 k x 128 cols)
#pragma unroll
        for (int l = 0; l < 4; l++) {
            int idx = tid + l * 256;          // 0..1023
            int k   = idx >> 5;               // 32 float4 per row
            int j4  = idx & 31;
            float4 v = *reinterpret_cast<const float4*>(
                           &w1[(size_t)(kk + k) * HHALF + j4 * 4]);
            ws[k][j4 * 4 + 0] = v.x;
            ws[k][j4 * 4 + 1] = v.y;
            ws[k][j4 * 4 + 2] = v.z;
            ws[k][j4 * 4 + 3] = v.w;
        }
        __syncthreads();

#pragma unroll
        for (int k = 0; k < KC; k++) {
            float a[8], b[8];
#pragma unroll
            for (int i = 0; i < 8; i++) a[i] = xs[ty * 8 + i][k];
#pragma unroll
            for (int j = 0; j < 8; j++) b[j] = ws[k][tx * 8 + j];
#pragma unroll
            for (int i = 0; i < 8; i++)
#pragma unroll
                for (int j = 0; j < 8; j++)
                    acc[i][j] = fmaf(a[i], b[j], acc[i][j]);
        }
        __syncthreads();
    }

    // epilogue: tanh + dot with w2 per row, reduce across the 16 tx-groups
    float b1r[8], w2r[8];
#pragma unroll
    for (int j = 0; j < 8; j++) {
        b1r[j] = b1[tx * 8 + j];
        w2r[j] = w2[tx * 8 + j];
    }
#pragma unroll
    for (int i = 0; i < 8; i++) {
        float s = 0.0f;
#pragma unroll
        for (int j = 0; j < 8; j++)
            s = fmaf(tanhf(acc[i][j] + b1r[j]), w2r[j], s);
        sred[tx][ty * 8 + i] = s;
    }
    __syncthreads();

    if (tid < TM) {
        int node = row0 + tid;
        if (node < n) {
            float s = 0.0f;
#pragma unroll
            for (int t = 0; t < 16; t++) s += sred[t][tid];
            s += b2[0];
            g_scores[node] = s;
            int g = batch[node];
            if (g >= 0 && g < NGRAPH)
                atomicMaxF(&g_segmax[g], s);
        }
    }
}

// ---------------------------------------------------------------------------
// K2: e = exp(score - segmax[g]); segment-sum with warp aggregation.
// ---------------------------------------------------------------------------
__global__ void k_expsum(const int* __restrict__ batch, int n)
{
    int i = blockIdx.x * blockDim.x + threadIdx.x;
    bool valid = (i < n);
    int g = valid ? batch[i] : -1;
    if (g < 0 || g >= NGRAPH) g = -1;
    float e = 0.0f;
    if (valid && g >= 0) {
        e = expf(g_scores[i] - g_segmax[g]);
        g_scores[i] = e;   // store e in place
    }

    const unsigned full = 0xffffffffu;
    int g0 = __shfl_sync(full, g, 0);
    bool uniform = __all_sync(full, g == g0);
    if (uniform && g0 >= 0) {
        float s = e;
#pragma unroll
        for (int off = 16; off; off >>= 1)
            s += __shfl_down_sync(full, s, off);
        if ((threadIdx.x & 31) == 0)
            atomicAdd(&g_segsum[g0], s);
    } else if (g >= 0) {
        atomicAdd(&g_segsum[g], e);
    }
}

// ---------------------------------------------------------------------------
// K3: attention-weighted pooling. One block per graph; binary search bounds
// on sorted batch; one thread per output column; single clean write of out.
// ---------------------------------------------------------------------------
__global__ __launch_bounds__(256) void k_pool(
    const float* __restrict__ x,
    const int* __restrict__ batch,
    float* __restrict__ out,
    int n)
{
    const int b = blockIdx.x;   // graph id
    // lower_bound(batch, b)
    int lo = 0, hi = n;
    while (lo < hi) { int mid = (lo + hi) >> 1; if (batch[mid] < b) lo = mid + 1; else hi = mid; }
    const int start = lo;
    // lower_bound(batch, b+1)
    hi = n;
    while (lo < hi) { int mid = (lo + hi) >> 1; if (batch[mid] < b + 1) lo = mid + 1; else hi = mid; }
    const int end = lo;

    const int col = threadIdx.x;
    float acc = 0.0f;
    int node = start;
    // unroll-by-4 to get memory-level parallelism
    for (; node + 4 <= end; node += 4) {
        float e0 = g_scores[node + 0];
        float e1 = g_scores[node + 1];
        float e2 = g_scores[node + 2];
        float e3 = g_scores[node + 3];
        float x0 = x[(size_t)(node + 0) * HID + col];
        float x1 = x[(size_t)(node + 1) * HID + col];
        float x2 = x[(size_t)(node + 2) * HID + col];
        float x3 = x[(size_t)(node + 3) * HID + col];
        acc = fmaf(e0, x0, acc);
        acc = fmaf(e1, x1, acc);
        acc = fmaf(e2, x2, acc);
        acc = fmaf(e3, x3, acc);
    }
    for (; node < end; node++)
        acc = fmaf(g_scores[node], x[(size_t)node * HID + col], acc);

    float result = 0.0f;
    if (end > start)
        result = acc / g_segsum[b];
    out[(size_t)b * HID + col] = result;
}

// ---------------------------------------------------------------------------
extern "C" void kernel_launch(void* const* d_in, const int* in_sizes, int n_in,
                              void* d_out, int out_size)
{
    const float* x     = (const float*)d_in[0];
    const int*   batch = (const int*)d_in[1];
    const float* w1    = (const float*)d_in[2];
    const float* b1    = (const float*)d_in[3];
    const float* w2    = (const float*)d_in[4];
    const float* b2    = (const float*)d_in[5];
    float*       out   = (float*)d_out;

    const int n = in_sizes[1];   // number of nodes (batch element count)

    k_init<<<(NGRAPH + 255) / 256, 256>>>();
    k_scores<<<(n + TM - 1) / TM, 256>>>(x, batch, w1, b1, w2, b2, n);
    k_expsum<<<(n + 255) / 256, 256>>>(batch, n);
    k_pool<<<NGRAPH, 256>>>(x, batch, out, n);
}

// round 4
// speedup vs baseline: 1.8560x; 1.8560x over previous
#include <cuda_runtime.h>
#include <cuda_bf16.h>
#include <stdint.h>
#include <math.h>

#define NNODES  1000000
#define HID     256
#define HHALF   128
#define NGRAPH  1024

// ---- scratch (no allocations allowed) ----
__device__ float g_scores[NNODES];            // scores, then exp(score - max)
__device__ float g_segmax[NGRAPH];
__device__ float g_segsum[NGRAPH];
__device__ __nv_bfloat16 g_whT[HHALF * HID];  // w1 hi, transposed [n][k]
__device__ __nv_bfloat16 g_wlT[HHALF * HID];  // w1 lo, transposed [n][k]

__device__ __forceinline__ void atomicMaxF(float* addr, float v) {
    if (v >= 0.0f) atomicMax((int*)addr, __float_as_int(v));
    else           atomicMin((unsigned int*)addr, __float_as_uint(v));
}

__device__ __forceinline__ float tanh_fast(float x) {
    float y; asm("tanh.approx.f32 %0, %1;" : "=f"(y) : "f"(x)); return y;
}

#define MMA_BF16(c, a, b0, b1)                                              \
    asm volatile("mma.sync.aligned.m16n8k16.row.col.f32.bf16.bf16.f32 "     \
                 "{%0,%1,%2,%3}, {%4,%5,%6,%7}, {%8,%9}, {%0,%1,%2,%3};"    \
                 : "+f"(c[0]), "+f"(c[1]), "+f"(c[2]), "+f"(c[3])           \
                 : "r"(a[0]), "r"(a[1]), "r"(a[2]), "r"(a[3]),              \
                   "r"(b0), "r"(b1))

// ---------------------------------------------------------------------------
// K0a: init per-graph reductions
// ---------------------------------------------------------------------------
__global__ void k_init() {
    int i = blockIdx.x * blockDim.x + threadIdx.x;
    if (i < NGRAPH) {
        g_segmax[i] = -INFINITY;
        g_segsum[i] = 0.0f;
    }
}

// ---------------------------------------------------------------------------
// K0b: split w1 into hi/lo bf16, transposed to [n][k]
// ---------------------------------------------------------------------------
__global__ void k_prep(const float* __restrict__ w1) {
    int i = blockIdx.x * blockDim.x + threadIdx.x;
    if (i < HID * HHALF) {
        int k = i >> 7, nn = i & 127;
        float v = w1[i];
        __nv_bfloat16 h = __float2bfloat16(v);
        __nv_bfloat16 l = __float2bfloat16(v - __bfloat162float(h));
        g_whT[nn * HID + k] = h;
        g_wlT[nn * HID + k] = l;
    }
}

// ---------------------------------------------------------------------------
// K1: fused scores = tanh(x @ w1 + b1) @ w2 + b2 with bf16-split tensor MMA.
// 128-row tiles x 128 cols, K=256 in chunks of 32. 8 warps: 4 in M, 2 in N.
// ---------------------------------------------------------------------------
#define TM 128
#define KC 32
#define SP 40   // padded SMEM stride (bf16 elems): conflict-free fragment loads

__global__ __launch_bounds__(256, 1) void k_scores(
    const float* __restrict__ x,
    const int* __restrict__ batch,
    const float* __restrict__ b1,
    const float* __restrict__ w2,
    const float* __restrict__ b2,
    int n)
{
    __shared__ __nv_bfloat16 xsh[TM * SP];
    __shared__ __nv_bfloat16 xsl[TM * SP];
    __shared__ __nv_bfloat16 wsh[HHALF * SP];
    __shared__ __nv_bfloat16 wsl[HHALF * SP];
    __shared__ float s_b1[HHALF], s_w2[HHALF];
    __shared__ float s_red[2][TM];

    const int tid  = threadIdx.x;
    const int lane = tid & 31;
    const int warp = tid >> 5;
    const int wm   = warp >> 1;      // 0..3 (M)
    const int wn   = warp & 1;       // 0..1 (N)
    const int g    = lane >> 2;      // group 0..7
    const int tq   = lane & 3;       // 0..3
    const int row0 = blockIdx.x * TM;

    if (tid < HHALF) { s_b1[tid] = b1[tid]; s_w2[tid] = w2[tid]; }

    float acc[2][8][4];
#pragma unroll
    for (int mt = 0; mt < 2; mt++)
#pragma unroll
        for (int nt = 0; nt < 8; nt++)
#pragma unroll
            for (int c = 0; c < 4; c++) acc[mt][nt][c] = 0.0f;

    // prefetch registers
    float4 xf[4];
    uint4  whr[2], wlr[2];

    // ---- pipelined k-chunk loop ----
#pragma unroll 1
    for (int ch = 0; ch < HID / KC + 1; ch++) {
        // issue global loads for chunk ch
        if (ch < HID / KC) {
            const int kk = ch * KC;
#pragma unroll
            for (int l = 0; l < 4; l++) {
                int idx = tid + l * 256;
                int m = idx >> 3, c4 = idx & 7;
                int node = row0 + m;
                xf[l] = (node < n)
                    ? *reinterpret_cast<const float4*>(&x[(size_t)node * HID + kk + c4 * 4])
                    : make_float4(0.f, 0.f, 0.f, 0.f);
            }
#pragma unroll
            for (int l = 0; l < 2; l++) {
                int idx = tid + l * 256;    // 0..511
                int nn = idx >> 2, kq = idx & 3;
                whr[l] = *reinterpret_cast<const uint4*>(&g_whT[nn * HID + kk + kq * 8]);
                wlr[l] = *reinterpret_cast<const uint4*>(&g_wlT[nn * HID + kk + kq * 8]);
            }
        }

        // compute on chunk ch-1 (already in SMEM)
        if (ch > 0) {
#pragma unroll
            for (int ks = 0; ks < 2; ks++) {
                const int k0 = ks * 16;
                uint32_t A[2][2][4];
#pragma unroll
                for (int mt = 0; mt < 2; mt++) {
                    int r  = wm * 32 + mt * 16 + g;
                    int kc = k0 + tq * 2;
                    A[mt][0][0] = *(const uint32_t*)&xsh[r * SP + kc];
                    A[mt][0][1] = *(const uint32_t*)&xsh[(r + 8) * SP + kc];
                    A[mt][0][2] = *(const uint32_t*)&xsh[r * SP + kc + 8];
                    A[mt][0][3] = *(const uint32_t*)&xsh[(r + 8) * SP + kc + 8];
                    A[mt][1][0] = *(const uint32_t*)&xsl[r * SP + kc];
                    A[mt][1][1] = *(const uint32_t*)&xsl[(r + 8) * SP + kc];
                    A[mt][1][2] = *(const uint32_t*)&xsl[r * SP + kc + 8];
                    A[mt][1][3] = *(const uint32_t*)&xsl[(r + 8) * SP + kc + 8];
                }
#pragma unroll
                for (int nt = 0; nt < 8; nt++) {
                    int nn = wn * 64 + nt * 8 + g;
                    int kc = k0 + tq * 2;
                    uint32_t bh0 = *(const uint32_t*)&wsh[nn * SP + kc];
                    uint32_t bh1 = *(const uint32_t*)&wsh[nn * SP + kc + 8];
                    uint32_t bl0 = *(const uint32_t*)&wsl[nn * SP + kc];
                    uint32_t bl1 = *(const uint32_t*)&wsl[nn * SP + kc + 8];
#pragma unroll
                    for (int mt = 0; mt < 2; mt++) {
                        MMA_BF16(acc[mt][nt], A[mt][0], bh0, bh1);  // xh*wh
                        MMA_BF16(acc[mt][nt], A[mt][1], bh0, bh1);  // xl*wh
                        MMA_BF16(acc[mt][nt], A[mt][0], bl0, bl1);  // xh*wl
                    }
                }
            }
            __syncthreads();   // compute done before overwriting SMEM
        }

        // store chunk ch to SMEM (split to hi/lo bf16)
        if (ch < HID / KC) {
#pragma unroll
            for (int l = 0; l < 4; l++) {
                int idx = tid + l * 256;
                int m = idx >> 3, c4 = idx & 7;
                float v[4] = { xf[l].x, xf[l].y, xf[l].z, xf[l].w };
                __nv_bfloat16 h[4], lo[4];
#pragma unroll
                for (int j = 0; j < 4; j++) {
                    h[j]  = __float2bfloat16(v[j]);
                    lo[j] = __float2bfloat16(v[j] - __bfloat162float(h[j]));
                }
#pragma unroll
                for (int j = 0; j < 4; j += 2) {
                    __nv_bfloat162 ph = __nv_bfloat162(h[j], h[j + 1]);
                    __nv_bfloat162 pl = __nv_bfloat162(lo[j], lo[j + 1]);
                    *(__nv_bfloat162*)&xsh[m * SP + c4 * 4 + j] = ph;
                    *(__nv_bfloat162*)&xsl[m * SP + c4 * 4 + j] = pl;
                }
            }
#pragma unroll
            for (int l = 0; l < 2; l++) {
                int idx = tid + l * 256;
                int nn = idx >> 2, kq = idx & 3;
                *(uint4*)&wsh[nn * SP + kq * 8] = whr[l];
                *(uint4*)&wsl[nn * SP + kq * 8] = wlr[l];
            }
            __syncthreads();   // SMEM ready for next iteration's compute
        }
    }

    // ---- epilogue: tanh + dot(w2), reduce to one scalar per row ----
    float rp[4] = {0.f, 0.f, 0.f, 0.f};   // [mt*2 + (0: row g, 1: row g+8)]
#pragma unroll
    for (int nt = 0; nt < 8; nt++) {
        int n0 = wn * 64 + nt * 8 + tq * 2;
        float b1a = s_b1[n0], b1b = s_b1[n0 + 1];
        float w2a = s_w2[n0], w2b = s_w2[n0 + 1];
#pragma unroll
        for (int mt = 0; mt < 2; mt++) {
            rp[mt * 2 + 0] += tanh_fast(acc[mt][nt][0] + b1a) * w2a
                            + tanh_fast(acc[mt][nt][1] + b1b) * w2b;
            rp[mt * 2 + 1] += tanh_fast(acc[mt][nt][2] + b1a) * w2a
                            + tanh_fast(acc[mt][nt][3] + b1b) * w2b;
        }
    }
#pragma unroll
    for (int i = 0; i < 4; i++) {
        rp[i] += __shfl_xor_sync(0xffffffffu, rp[i], 1);
        rp[i] += __shfl_xor_sync(0xffffffffu, rp[i], 2);
    }
    if (tq == 0) {
#pragma unroll
        for (int mt = 0; mt < 2; mt++) {
            s_red[wn][wm * 32 + mt * 16 + g]     = rp[mt * 2 + 0];
            s_red[wn][wm * 32 + mt * 16 + g + 8] = rp[mt * 2 + 1];
        }
    }
    __syncthreads();

    if (tid < TM) {
        int node = row0 + tid;
        if (node < n) {
            float s = s_red[0][tid] + s_red[1][tid] + b2[0];
            g_scores[node] = s;
            int gg = batch[node];
            if (gg >= 0 && gg < NGRAPH)
                atomicMaxF(&g_segmax[gg], s);
        }
    }
}

// ---------------------------------------------------------------------------
// K2: e = exp(score - segmax[g]); segment-sum with warp aggregation.
// ---------------------------------------------------------------------------
__global__ void k_expsum(const int* __restrict__ batch, int n)
{
    int i = blockIdx.x * blockDim.x + threadIdx.x;
    bool valid = (i < n);
    int g = valid ? batch[i] : -1;
    if (g < 0 || g >= NGRAPH) g = -1;
    float e = 0.0f;
    if (valid && g >= 0) {
        e = expf(g_scores[i] - g_segmax[g]);
        g_scores[i] = e;
    }

    const unsigned full = 0xffffffffu;
    int g0 = __shfl_sync(full, g, 0);
    bool uniform = __all_sync(full, g == g0);
    if (uniform && g0 >= 0) {
        float s = e;
#pragma unroll
        for (int off = 16; off; off >>= 1)
            s += __shfl_down_sync(full, s, off);
        if ((threadIdx.x & 31) == 0)
            atomicAdd(&g_segsum[g0], s);
    } else if (g >= 0) {
        atomicAdd(&g_segsum[g], e);
    }
}

// ---------------------------------------------------------------------------
// K3: attention-weighted pooling. One block per graph, 512 threads:
// 2 nodes per iteration x 256 cols, unrolled x4 -> 8 rows in flight.
// ---------------------------------------------------------------------------
__global__ __launch_bounds__(512) void k_pool(
    const float* __restrict__ x,
    const int* __restrict__ batch,
    float* __restrict__ out,
    int n)
{
    const int b = blockIdx.x;
    int lo = 0, hi = n;
    while (lo < hi) { int mid = (lo + hi) >> 1; if (batch[mid] < b) lo = mid + 1; else hi = mid; }
    const int start = lo;
    hi = n;
    while (lo < hi) { int mid = (lo + hi) >> 1; if (batch[mid] < b + 1) lo = mid + 1; else hi = mid; }
    const int end = lo;

    const int col  = threadIdx.x & 255;
    const int half = threadIdx.x >> 8;

    float acc = 0.0f;
    int node = start + half;
    for (; node + 6 < end; node += 8) {
        float e0 = g_scores[node + 0];
        float e1 = g_scores[node + 2];
        float e2 = g_scores[node + 4];
        float e3 = g_scores[node + 6];
        float x0 = x[(size_t)(node + 0) * HID + col];
        float x1 = x[(size_t)(node + 2) * HID + col];
        float x2 = x[(size_t)(node + 4) * HID + col];
        float x3 = x[(size_t)(node + 6) * HID + col];
        acc = fmaf(e0, x0, acc);
        acc = fmaf(e1, x1, acc);
        acc = fmaf(e2, x2, acc);
        acc = fmaf(e3, x3, acc);
    }
    for (; node < end; node += 2)
        acc = fmaf(g_scores[node], x[(size_t)node * HID + col], acc);

    __shared__ float sp[512];
    sp[threadIdx.x] = acc;
    __syncthreads();
    if (threadIdx.x < 256) {
        float r = sp[threadIdx.x] + sp[threadIdx.x + 256];
        out[(size_t)b * HID + threadIdx.x] = (end > start) ? r / g_segsum[b] : 0.0f;
    }
}

// ---------------------------------------------------------------------------
extern "C" void kernel_launch(void* const* d_in, const int* in_sizes, int n_in,
                              void* d_out, int out_size)
{
    const float* x     = (const float*)d_in[0];
    const int*   batch = (const int*)d_in[1];
    const float* w1    = (const float*)d_in[2];
    const float* b1    = (const float*)d_in[3];
    const float* w2    = (const float*)d_in[4];
    const float* b2    = (const float*)d_in[5];
    float*       out   = (float*)d_out;

    const int n = in_sizes[1];

    k_init<<<(NGRAPH + 255) / 256, 256>>>();
    k_prep<<<(HID * HHALF + 255) / 256, 256>>>(w1);
    k_scores<<<(n + TM - 1) / TM, 256>>>(x, batch, b1, w2, b2, n);
    k_expsum<<<(n + 255) / 256, 256>>>(batch, n);
    k_pool<<<NGRAPH, 512>>>(x, batch, out, n);
}

// round 6
// speedup vs baseline: 2.0986x; 1.1307x over previous
#include <cuda_runtime.h>
#include <cuda_bf16.h>
#include <stdint.h>
#include <math.h>

#define NNODES  1000000
#define HID     256
#define HHALF   128
#define NGRAPH  1024

// ---- scratch (no allocations allowed) ----
__device__ float g_scores[NNODES];        // scores, then exp(score - max)
__device__ float g_segmax[NGRAPH];
__device__ float g_segsum[NGRAPH];
__device__ float g_wT[HHALF * HID];       // w1 tf32-rounded (bias-comp), [n][k]

__device__ __forceinline__ void atomicMaxF(float* addr, float v) {
    if (v >= 0.0f) atomicMax((int*)addr, __float_as_int(v));
    else           atomicMin((unsigned int*)addr, __float_as_uint(v));
}

__device__ __forceinline__ float tanh_fast(float x) {
    float y; asm("tanh.approx.f32 %0, %1;" : "=f"(y) : "f"(x)); return y;
}

// warp-level tf32 MMA (sm_80+ baseline PTX; operands are raw 32-bit regs,
// HW truncates fp32 -> tf32 internally)
#define MMA_TF32(c, a, b0, b1)                                              \
    asm volatile("mma.sync.aligned.m16n8k8.row.col.f32.tf32.tf32.f32 "      \
                 "{%0,%1,%2,%3}, {%4,%5,%6,%7}, {%8,%9}, {%0,%1,%2,%3};"    \
                 : "+f"(c[0]), "+f"(c[1]), "+f"(c[2]), "+f"(c[3])           \
                 : "r"(a[0]), "r"(a[1]), "r"(a[2]), "r"(a[3]),              \
                   "r"(b0), "r"(b1))

// ---------------------------------------------------------------------------
// K0a: init per-graph reductions
// ---------------------------------------------------------------------------
__global__ void k_init() {
    int i = blockIdx.x * blockDim.x + threadIdx.x;
    if (i < NGRAPH) { g_segmax[i] = -INFINITY; g_segsum[i] = 0.0f; }
}

// ---------------------------------------------------------------------------
// K0b: w1 [k][n] -> g_wT [n][k], RNA-rounded to tf32, pre-scaled by 1.00034
// to compensate the truncation bias of raw-fp32 x inside the MMA.
// ---------------------------------------------------------------------------
__global__ void k_prep(const float* __restrict__ w1) {
    int i = blockIdx.x * blockDim.x + threadIdx.x;
    if (i < HID * HHALF) {
        int k = i >> 7, nn = i & 127;
        float v = w1[i] * 1.00034f;
        uint32_t r;
        asm("cvt.rna.tf32.f32 %0, %1;" : "=r"(r) : "f"(v));
        g_wT[nn * HID + k] = __uint_as_float(r);
    }
}

// ---------------------------------------------------------------------------
// K1: scores = tanh(x @ w1 + b1) @ w2 + b2 via tf32 mma.sync.
// Tile 128 nodes x 128 cols, K=256 in chunks of 32. 8 warps: 4 in M, 2 in N.
// x goes gmem -> SMEM as raw fp32 (ZERO conversion instructions).
// ---------------------------------------------------------------------------
#define TM 128
#define KC 32
#define SP 36   // float stride: lane addr (4g+tq) mod 32 -> conflict-free

__global__ __launch_bounds__(256) void k_scores(
    const float* __restrict__ x,
    const int* __restrict__ batch,
    const float* __restrict__ b1,
    const float* __restrict__ w2,
    const float* __restrict__ b2,
    int n)
{
    __shared__ float xs[TM * SP];       // 18432 B
    __shared__ float ws[HHALF * SP];    // 18432 B
    __shared__ float s_b1[HHALF], s_w2[HHALF];
    __shared__ float s_red[2][TM];

    const int tid  = threadIdx.x;
    const int lane = tid & 31;
    const int warp = tid >> 5;
    const int wm   = warp >> 1;      // 0..3 (M)
    const int wn   = warp & 1;       // 0..1 (N)
    const int g    = lane >> 2;      // 0..7
    const int tq   = lane & 3;       // 0..3
    const int row0 = blockIdx.x * TM;

    if (tid < HHALF) { s_b1[tid] = b1[tid]; s_w2[tid] = w2[tid]; }

    float acc[2][8][4];
#pragma unroll
    for (int mt = 0; mt < 2; mt++)
#pragma unroll
        for (int nt = 0; nt < 8; nt++)
#pragma unroll
            for (int c = 0; c < 4; c++) acc[mt][nt][c] = 0.0f;

    float4 xf[4], wf[4];   // prefetch registers

#pragma unroll 1
    for (int ch = 0; ch < HID / KC + 1; ch++) {
        // issue global loads for chunk ch
        if (ch < HID / KC) {
            const int kk = ch * KC;
#pragma unroll
            for (int l = 0; l < 4; l++) {
                int idx = tid + l * 256;
                int m = idx >> 3, c4 = idx & 7;
                int node = row0 + m;
                xf[l] = (node < n)
                    ? *reinterpret_cast<const float4*>(&x[(size_t)node * HID + kk + c4 * 4])
                    : make_float4(0.f, 0.f, 0.f, 0.f);
            }
#pragma unroll
            for (int l = 0; l < 4; l++) {
                int idx = tid + l * 256;
                int nn = idx >> 3, c4 = idx & 7;
                wf[l] = *reinterpret_cast<const float4*>(&g_wT[nn * HID + kk + c4 * 4]);
            }
        }

        // compute on chunk ch-1 (already in SMEM)
        if (ch > 0) {
#pragma unroll
            for (int ks = 0; ks < 4; ks++) {
                const int k0 = ks * 8;
                uint32_t A[2][4];
#pragma unroll
                for (int mt = 0; mt < 2; mt++) {
                    int r = wm * 32 + mt * 16 + g;
                    A[mt][0] = *(const uint32_t*)&xs[r * SP + k0 + tq];
                    A[mt][1] = *(const uint32_t*)&xs[(r + 8) * SP + k0 + tq];
                    A[mt][2] = *(const uint32_t*)&xs[r * SP + k0 + tq + 4];
                    A[mt][3] = *(const uint32_t*)&xs[(r + 8) * SP + k0 + tq + 4];
                }
#pragma unroll
                for (int nt = 0; nt < 8; nt++) {
                    int nn = wn * 64 + nt * 8 + g;
                    uint32_t b0 = *(const uint32_t*)&ws[nn * SP + k0 + tq];
                    uint32_t b1r = *(const uint32_t*)&ws[nn * SP + k0 + tq + 4];
                    MMA_TF32(acc[0][nt], A[0], b0, b1r);
                    MMA_TF32(acc[1][nt], A[1], b0, b1r);
                }
            }
            __syncthreads();   // compute done before overwriting SMEM
        }

        // store chunk ch to SMEM (raw fp32, no conversion)
        if (ch < HID / KC) {
#pragma unroll
            for (int l = 0; l < 4; l++) {
                int idx = tid + l * 256;
                int m = idx >> 3, c4 = idx & 7;
                *(float4*)&xs[m * SP + c4 * 4] = xf[l];
            }
#pragma unroll
            for (int l = 0; l < 4; l++) {
                int idx = tid + l * 256;
                int nn = idx >> 3, c4 = idx & 7;
                *(float4*)&ws[nn * SP + c4 * 4] = wf[l];
            }
            __syncthreads();   // SMEM ready for next iteration's compute
        }
    }

    // ---- epilogue: tanh + dot(w2), reduce to one scalar per row ----
    float rp[4] = {0.f, 0.f, 0.f, 0.f};
#pragma unroll
    for (int nt = 0; nt < 8; nt++) {
        int n0 = wn * 64 + nt * 8 + tq * 2;
        float b1a = s_b1[n0], b1b = s_b1[n0 + 1];
        float w2a = s_w2[n0], w2b = s_w2[n0 + 1];
#pragma unroll
        for (int mt = 0; mt < 2; mt++) {
            rp[mt * 2 + 0] += tanh_fast(acc[mt][nt][0] + b1a) * w2a
                            + tanh_fast(acc[mt][nt][1] + b1b) * w2b;
            rp[mt * 2 + 1] += tanh_fast(acc[mt][nt][2] + b1a) * w2a
                            + tanh_fast(acc[mt][nt][3] + b1b) * w2b;
        }
    }
#pragma unroll
    for (int i = 0; i < 4; i++) {
        rp[i] += __shfl_xor_sync(0xffffffffu, rp[i], 1);
        rp[i] += __shfl_xor_sync(0xffffffffu, rp[i], 2);
    }
    if (tq == 0) {
#pragma unroll
        for (int mt = 0; mt < 2; mt++) {
            s_red[wn][wm * 32 + mt * 16 + g]     = rp[mt * 2 + 0];
            s_red[wn][wm * 32 + mt * 16 + g + 8] = rp[mt * 2 + 1];
        }
    }
    __syncthreads();

    if (tid < TM) {
        int node = row0 + tid;
        if (node < n) {
            float s = s_red[0][tid] + s_red[1][tid] + b2[0];
            g_scores[node] = s;
            int gg = batch[node];
            if (gg >= 0 && gg < NGRAPH)
                atomicMaxF(&g_segmax[gg], s);
        }
    }
}

// ---------------------------------------------------------------------------
// K2: e = exp(score - segmax[g]); segment-sum with warp aggregation.
// ---------------------------------------------------------------------------
__global__ void k_expsum(const int* __restrict__ batch, int n)
{
    int i = blockIdx.x * blockDim.x + threadIdx.x;
    bool valid = (i < n);
    int g = valid ? batch[i] : -1;
    if (g < 0 || g >= NGRAPH) g = -1;
    float e = 0.0f;
    if (valid && g >= 0) {
        e = expf(g_scores[i] - g_segmax[g]);
        g_scores[i] = e;
    }
    const unsigned full = 0xffffffffu;
    int g0 = __shfl_sync(full, g, 0);
    bool uniform = __all_sync(full, g == g0);
    if (uniform && g0 >= 0) {
        float s = e;
#pragma unroll
        for (int off = 16; off; off >>= 1)
            s += __shfl_down_sync(full, s, off);
        if ((threadIdx.x & 31) == 0) atomicAdd(&g_segsum[g0], s);
    } else if (g >= 0) {
        atomicAdd(&g_segsum[g], e);
    }
}

// ---------------------------------------------------------------------------
// K3: attention-weighted pooling.
// ---------------------------------------------------------------------------
__global__ __launch_bounds__(512) void k_pool(
    const float* __restrict__ x,
    const int* __restrict__ batch,
    float* __restrict__ out,
    int n)
{
    const int b = blockIdx.x;
    int lo = 0, hi = n;
    while (lo < hi) { int mid = (lo + hi) >> 1; if (batch[mid] < b) lo = mid + 1; else hi = mid; }
    const int start = lo;
    hi = n;
    while (lo < hi) { int mid = (lo + hi) >> 1; if (batch[mid] < b + 1) lo = mid + 1; else hi = mid; }
    const int end = lo;

    const int col  = threadIdx.x & 255;
    const int half = threadIdx.x >> 8;

    float acc = 0.0f;
    int node = start + half;
    for (; node + 6 < end; node += 8) {
        float e0 = g_scores[node + 0];
        float e1 = g_scores[node + 2];
        float e2 = g_scores[node + 4];
        float e3 = g_scores[node + 6];
        float x0 = x[(size_t)(node + 0) * HID + col];
        float x1 = x[(size_t)(node + 2) * HID + col];
        float x2 = x[(size_t)(node + 4) * HID + col];
        float x3 = x[(size_t)(node + 6) * HID + col];
        acc = fmaf(e0, x0, acc);
        acc = fmaf(e1, x1, acc);
        acc = fmaf(e2, x2, acc);
        acc = fmaf(e3, x3, acc);
    }
    for (; node < end; node += 2)
        acc = fmaf(g_scores[node], x[(size_t)node * HID + col], acc);

    __shared__ float sp[512];
    sp[threadIdx.x] = acc;
    __syncthreads();
    if (threadIdx.x < 256) {
        float r = sp[threadIdx.x] + sp[threadIdx.x + 256];
        out[(size_t)b * HID + threadIdx.x] = (end > start) ? r / g_segsum[b] : 0.0f;
    }
}

// ---------------------------------------------------------------------------
extern "C" void kernel_launch(void* const* d_in, const int* in_sizes, int n_in,
                              void* d_out, int out_size)
{
    const float* x     = (const float*)d_in[0];
    const int*   batch = (const int*)d_in[1];
    const float* w1    = (const float*)d_in[2];
    const float* b1    = (const float*)d_in[3];
    const float* w2    = (const float*)d_in[4];
    const float* b2    = (const float*)d_in[5];
    float*       out   = (float*)d_out;

    const int n = in_sizes[1];

    k_init<<<(NGRAPH + 255) / 256, 256>>>();
    k_prep<<<(HID * HHALF + 255) / 256, 256>>>(w1);
    k_scores<<<(n + TM - 1) / TM, 256>>>(x, batch, b1, w2, b2, n);
    k_expsum<<<(n + 255) / 256, 256>>>(batch, n);
    k_pool<<<NGRAPH, 512>>>(x, batch, out, n);
}